// round 2
// baseline (speedup 1.0000x reference)
#include <cuda_runtime.h>
#include <math.h>

#define NBA 10
#define NCLS 14
#define LCH 19
#define NOBJ 256
#define BB 8
#define HH 96
#define WW 96
#define CC (NBA*LCH)          // 190
#define HWSZ (HH*WW)          // 9216
#define TOTAL (BB*NBA*HH*WW)  // 737280

__device__ float  g_iou[NOBJ*NBA];
__device__ double g_sum_all;

// ---------------------------------------------------------------------------
// K1: per-(grid, anchor) IoU between target box (anchor g) and pred box a,
// all at cell (b,h,w). Also zeroes the global double accumulator.
// ---------------------------------------------------------------------------
__global__ void k_iou(const float* __restrict__ P, const float* __restrict__ T,
                      const int* __restrict__ G) {
    int idx = blockIdx.x * blockDim.x + threadIdx.x;
    if (idx == 0) g_sum_all = 0.0;
    if (idx >= NOBJ * NBA) return;
    int i = idx / NBA, a = idx % NBA;
    int b = G[i*4+0], g = G[i*4+1], h = G[i*4+2], w = G[i*4+3];
    int base = h * WW + w;
    const float* Tg = T + (size_t)(b*CC + g*LCH)*HWSZ + base;
    float tx = Tg[1*HWSZ], ty = Tg[2*HWSZ], tw = Tg[3*HWSZ], th = Tg[4*HWSZ];
    const float* Pa = P + (size_t)(b*CC + a*LCH)*HWSZ + base;
    float px = Pa[1*HWSZ], py = Pa[2*HWSZ], pw = Pa[3*HWSZ], ph = Pa[4*HWSZ];
    float tx1 = tx - tw*0.5f, ty1 = ty - th*0.5f, tx2 = tx + tw*0.5f, ty2 = ty + th*0.5f;
    float px1 = px - pw*0.5f, py1 = py - ph*0.5f, px2 = px + pw*0.5f, py2 = py + ph*0.5f;
    float x1 = fmaxf(tx1, px1), y1 = fmaxf(ty1, py1);
    float x2 = fminf(tx2, px2), y2 = fminf(ty2, py2);
    float inter = fmaxf(x2 - x1, 0.0f) * fmaxf(y2 - y1, 0.0f);
    float a1 = fabsf((tx2 - tx1) * (ty2 - ty1));
    float a2 = fabsf((px2 - px1) * (py2 - py1));
    g_iou[idx] = inter / (a1 + a2 - inter + 1e-6f);
}

// ---------------------------------------------------------------------------
// K2: sum of (tc - pc)^2 over all (b, anchor, h, w). Channel planes are
// contiguous 9216-float blocks -> float4 loads. One double atomicAdd / block.
// ---------------------------------------------------------------------------
__global__ void k_reduce(const float* __restrict__ P, const float* __restrict__ T) {
    int idx = blockIdx.x * blockDim.x + threadIdx.x;  // 0 .. TOTAL/4-1
    float s = 0.0f;
    if (idx < TOTAL/4) {
        int plane = idx / (HWSZ/4);
        int off   = idx % (HWSZ/4);
        int b = plane / NBA, a = plane % NBA;
        size_t base = (size_t)(b*CC + a*LCH) * HWSZ + (size_t)off * 4;
        float4 t = *reinterpret_cast<const float4*>(T + base);
        float4 p = *reinterpret_cast<const float4*>(P + base);
        float dx = t.x - p.x, dy = t.y - p.y, dz = t.z - p.z, dw = t.w - p.w;
        s = dx*dx + dy*dy + dz*dz + dw*dw;
    }
    #pragma unroll
    for (int o = 16; o; o >>= 1) s += __shfl_down_sync(0xffffffffu, s, o);
    __shared__ float ws[8];
    int lane = threadIdx.x & 31, wd = threadIdx.x >> 5;
    if (lane == 0) ws[wd] = s;
    __syncthreads();
    if (threadIdx.x == 0) {
        float bs = 0.0f;
        #pragma unroll
        for (int k = 0; k < 8; k++) bs += ws[k];
        atomicAdd(&g_sum_all, (double)bs);
    }
}

// ---------------------------------------------------------------------------
// K3: one block, 256 threads. Sequential anchor selection (exact emulation of
// the reference scan, collapsed to "first a>=1 with iou>0 and a not in row"),
// sel_xy lookup, dedup of zeroed positions, per-grid loss gathers, combine.
// ---------------------------------------------------------------------------
__global__ void k_final(const float* __restrict__ P, const float* __restrict__ T,
                        const int* __restrict__ G, float* __restrict__ out) {
    __shared__ int   sB[NOBJ], sG[NOBJ], sH[NOBJ], sW[NOBJ];
    __shared__ float sIou[NOBJ*NBA];
    __shared__ int   sSel[NOBJ], sSelxy[NOBJ], sIndep[NOBJ];
    __shared__ int   sMask[BB*NBA*NBA];   // anchor-presence bitmask per write-row (b,g,h)
    __shared__ float sRed[4][8];
    int tid = threadIdx.x;

    sB[tid] = G[tid*4+0]; sG[tid] = G[tid*4+1];
    sH[tid] = G[tid*4+2]; sW[tid] = G[tid*4+3];
    for (int k = tid; k < NOBJ*NBA; k += 256) sIou[k] = g_iou[k];
    for (int k = tid; k < BB*NBA*NBA; k += 256) sMask[k] = 0;
    __syncthreads();

    // Independent result: first anchor a>=1 with iou>0 (valid whenever the
    // read-row (b,h,w) can never have been written, i.e. w >= NBA).
    {
        int r = 0;
        #pragma unroll
        for (int a = 1; a < NBA; a++)
            if (r == 0 && sIou[tid*NBA + a] > 0.0f) r = a;
        sIndep[tid] = r;
    }
    __syncthreads();

    // Sequential pass in scan order (thread 0). Only grids with w < NBA can
    // observe prior writes; all writes update sMask at write-row (b,g,h).
    if (tid == 0) {
        for (int i = 0; i < NOBJ; i++) {
            int b = sB[i], g = sG[i], h = sH[i], w = sW[i];
            int res;
            if (w < NBA) {
                int m = sMask[(b*NBA + h)*NBA + w];
                res = 0;
                #pragma unroll
                for (int a = 1; a < NBA; a++)
                    if (res == 0 && sIou[i*NBA + a] > 0.0f && !((m >> a) & 1))
                        res = a;
            } else {
                res = sIndep[i];
            }
            if (res) sMask[(b*NBA + g)*NBA + h] |= (1 << res);
            sSel[i] = res;
        }
    }
    __syncthreads();

    // sel_xy[i] = final maxI[b, g, h, h]  (bug-preserved double-h index):
    // nonzero only if grid (b, g, h, w=h) exists.
    {
        int b = sB[tid], g = sG[tid], h = sH[tid];
        int v = 0;
        for (int j = 0; j < NOBJ; j++)
            if (sB[j] == b && sG[j] == g && sH[j] == h && sW[j] == h) v = sSel[j];
        sSelxy[tid] = v;
    }
    __syncthreads();

    // Per-grid loss terms.
    int b = sB[tid], g = sG[tid], h = sH[tid], w = sW[tid];
    int sel = sSel[tid], sxy = sSelxy[tid];
    int base = h * WW + w;
    const float* Tg = T + (size_t)(b*CC + g*LCH)*HWSZ + base;
    float tc = Tg[0],       tx = Tg[1*HWSZ], ty = Tg[2*HWSZ];
    float tw = Tg[3*HWSZ],  th = Tg[4*HWSZ];
    const float* Pxy = P + (size_t)(b*CC + sxy*LCH)*HWSZ + base;
    float px = Pxy[1*HWSZ], py = Pxy[2*HWSZ];
    const float* Ps = P + (size_t)(b*CC + sel*LCH)*HWSZ + base;
    float pc = Ps[0], pw = Ps[3*HWSZ], ph = Ps[4*HWSZ];

    float xl = (tx - px) * (tx - px);
    float yl = (ty - py) * (ty - py);
    float swt = sqrtf(fmaxf(tw, 0.0f)), swp = sqrtf(fmaxf(pw, 0.0f));
    float sht = sqrtf(fmaxf(th, 0.0f)), shp = sqrtf(fmaxf(ph, 0.0f));
    float wl = (swt - swp) * (swt - swp);
    float hl = (sht - shp) * (sht - shp);
    float loc  = xl + yl + wl + hl;
    float cobj = (tc - pc) * (tc - pc);

    // Class loss: preds at channel sel*LC+5+c, targets at channel b*LC+5+c
    // (bug-preserved: batch index used as anchor index for targets).
    const float* Tcls = T + (size_t)(b*CC + b*LCH + 5)*HWSZ + base;
    const float* Pcls = Ps + (size_t)5 * HWSZ;
    float cls = 0.0f;
    #pragma unroll
    for (int c = 0; c < NCLS; c++) {
        float d = Pcls[(size_t)c*HWSZ] - Tcls[(size_t)c*HWSZ];
        cls += d * d;
    }
    cls *= (1.0f / NCLS);

    // Correction for conf_nothing: subtract (tc-pc)^2 at distinct zeroed
    // positions (b, sel, h, w). Dedup: first occurrence in scan order wins.
    float tcs = T[(size_t)(b*CC + sel*LCH)*HWSZ + base];
    float corr = (tcs - pc) * (tcs - pc);
    for (int j = 0; j < tid; j++)
        if (sB[j] == b && sH[j] == h && sW[j] == w && sSel[j] == sel) { corr = 0.0f; break; }

    // Block reduction of the 4 partial sums.
    float v0 = loc, v1 = cobj, v2 = cls, v3 = corr;
    #pragma unroll
    for (int o = 16; o; o >>= 1) {
        v0 += __shfl_down_sync(0xffffffffu, v0, o);
        v1 += __shfl_down_sync(0xffffffffu, v1, o);
        v2 += __shfl_down_sync(0xffffffffu, v2, o);
        v3 += __shfl_down_sync(0xffffffffu, v3, o);
    }
    int lane = tid & 31, wd = tid >> 5;
    if (lane == 0) { sRed[0][wd] = v0; sRed[1][wd] = v1; sRed[2][wd] = v2; sRed[3][wd] = v3; }
    __syncthreads();
    if (tid == 0) {
        float L = 0, Cq = 0, Cl = 0, Co = 0;
        #pragma unroll
        for (int k = 0; k < 8; k++) {
            L += sRed[0][k]; Cq += sRed[1][k]; Cl += sRed[2][k]; Co += sRed[3][k];
        }
        double nothing = (g_sum_all - (double)Co) / (double)TOTAL;
        float loss = 7.0f * (L / NOBJ) + 5.0f * (Cq / NOBJ)
                   + 5.0f * (float)nothing + (Cl / NOBJ);
        out[0] = loss;
    }
}

extern "C" void kernel_launch(void* const* d_in, const int* in_sizes, int n_in,
                              void* d_out, int out_size) {
    const float* P = (const float*)d_in[0];
    const float* T = (const float*)d_in[1];
    const int*   G = (const int*)d_in[2];
    float* out = (float*)d_out;

    k_iou<<<(NOBJ*NBA + 255) / 256, 256>>>(P, T, G);
    k_reduce<<<(TOTAL/4 + 255) / 256, 256>>>(P, T);
    k_final<<<1, 256>>>(P, T, G, out);
}